// round 6
// baseline (speedup 1.0000x reference)
#include <cuda_runtime.h>
#include <math.h>
#include <stdint.h>

#define NB 256
#define NI 512   // outputs (i)
#define NJ 512   // inputs  (j) -> contraction K
#define NW 64

// drop in w-grouped layout: [wg][i][j][4w], float4 per (i,j). 67 MB scratch.
__device__ float g_dropP[(size_t)NW * NI * NJ];

__device__ __forceinline__ float tf32r(float x) {
    uint32_t u; asm("cvt.rna.tf32.f32 %0, %1;" : "=r"(u) : "f"(x));
    return __uint_as_float(u);
}
__device__ __forceinline__ uint32_t tf32u(float x) {
    uint32_t u; asm("cvt.rna.tf32.f32 %0, %1;" : "=r"(u) : "f"(x));
    return u;
}

// ---------------------------------------------------------------------------
// Kernel 1: dropP[wg][i][j][4], tf32-rounded.
// denom2 = 1 - 2 at cos + at^2.  Kerr term (~2.7e-19 rad) below fp32 eps.
// __cosf (MUFU): abs err ~1e-6 -> drop rel err <= ~1e-4 at resonance. Cheap.
// ---------------------------------------------------------------------------
__global__ void __launch_bounds__(256) dropP_kernel(
        const float* __restrict__ phase_shift,
        const float* __restrict__ coupling) {
    const int j = blockIdx.x * 256 + threadIdx.x;
    const int i = blockIdx.y;
    const int k = i * NJ + j;

    const double WLMIN = 1.53e-06, WLMAX = 1.57e-06;
    double c    = WLMIN + (WLMAX - WLMIN) * ((double)k / (double)(NI * NJ));
    double pref = (4.0 * M_PI * M_PI * 4.2 * 5e-06) / (c * c);   // 2*pi/fsr
    const float base = (float)(pref * (WLMIN - c)) + phase_shift[k];
    const float dphi = (float)(pref * ((WLMAX - WLMIN) / 63.0));

    float kap = fminf(fmaxf(coupling[k], 0.1f), 0.9f);
    float t   = sqrtf(1.0f - kap * kap);
    const float alpha = (float)(1.0 - M_PI / 15000.0);
    float at  = alpha * t;
    const float A2    = 1.0f + at * at;
    const float twoAt = 2.0f * at;
    const float coef  = kap * kap * alpha;

    float4* dst = (float4*)(g_dropP + ((size_t)i * NJ + j) * 4);
#pragma unroll
    for (int wg = 0; wg < NW / 4; wg++) {
        float4 v;
        float ph0 = fmaf((float)(4 * wg + 0), dphi, base);
        float ph1 = fmaf((float)(4 * wg + 1), dphi, base);
        float ph2 = fmaf((float)(4 * wg + 2), dphi, base);
        float ph3 = fmaf((float)(4 * wg + 3), dphi, base);
        v.x = tf32r(__fdividef(coef, A2 - twoAt * __cosf(ph0)));
        v.y = tf32r(__fdividef(coef, A2 - twoAt * __cosf(ph1)));
        v.z = tf32r(__fdividef(coef, A2 - twoAt * __cosf(ph2)));
        v.w = tf32r(__fdividef(coef, A2 - twoAt * __cosf(ph3)));
        dst[(size_t)wg * NI * NJ] = v;   // [wg][i][j][4] in float4 units
    }
}

// ---------------------------------------------------------------------------
// Kernel 2: fused GEMM over 4-w groups.
// out[b,i,w] = sum_j in[b,j,w] * drop[i,j,w], w in groups of 4 (VW=4).
// CTA: 256 thr / 8 warps, tile 64(b) x 128(i) x 4(w). Warp: 32x32x4w.
// A read straight from in[b][j][w4] (16B units); B from g_dropP (16B units).
// smem rows: 20 units of 16B (stride%8==4 -> LDS.128 phase-conflict-free).
// Epilogue: float4 w-vector stores straight to out. No transposes anywhere.
// ---------------------------------------------------------------------------
#define TM 64
#define TN 128
#define KC 16
#define NCH (NJ / KC)            // 32
#define RSU 20                   // 16B units per row
#define A_BYTES (TM * RSU * 16)  // 20480
#define B_BYTES (TN * RSU * 16)  // 40960
#define SMEM_REQ (2 * (A_BYTES + B_BYTES))  // 122880

#define CPA(s, g) asm volatile("cp.async.cg.shared.global [%0], [%1], 16;" :: "r"(s), "l"(g))

#define LDS128F(v, addr) \
    asm volatile("ld.shared.v4.f32 {%0,%1,%2,%3}, [%4];" \
        : "=f"((v).x), "=f"((v).y), "=f"((v).z), "=f"((v).w) : "r"(addr))

#define MMA_TF32(c, a0, a1, a2, a3, b0, b1) \
    asm volatile("mma.sync.aligned.m16n8k8.row.col.f32.tf32.tf32.f32 " \
        "{%0,%1,%2,%3}, {%4,%5,%6,%7}, {%8,%9}, {%0,%1,%2,%3};" \
        : "+f"((c)[0]), "+f"((c)[1]), "+f"((c)[2]), "+f"((c)[3]) \
        : "r"(a0), "r"(a1), "r"(a2), "r"(a3), "r"(b0), "r"(b1))

static __device__ __forceinline__ uint32_t smem_u32(const void* p) {
    uint32_t a;
    asm("{ .reg .u64 t; cvta.to.shared.u64 t, %1; cvt.u32.u64 %0, t; }" : "=r"(a) : "l"(p));
    return a;
}

__global__ void __launch_bounds__(256, 1) gemm_kernel(
        const float* __restrict__ in, float* __restrict__ out) {
    extern __shared__ float smem[];
    const uint32_t sbase = smem_u32(smem);
    const uint32_t sB    = sbase + 2 * A_BYTES;

    const int tid = threadIdx.x;
    const int wg  = blockIdx.x;            // w-group (w = 4*wg .. 4*wg+3)
    const int b0  = blockIdx.y * TM;
    const int i0  = blockIdx.z * TN;

    // gmem chunk bases (advance by KC in j)
    const float* gA = in + ((size_t)b0 * NJ) * NW + wg * 4;
    const float* gB = g_dropP + ((size_t)(wg * NI + i0) * NJ) * 4;

#define STAGE(parsel, ga, gb) do { \
    _Pragma("unroll") \
    for (int s = 0; s < 4; s++) { \
        int u = tid + (s << 8), bb = u >> 4, jj = u & 15; \
        CPA(sbase + (parsel) * A_BYTES + (uint32_t)(bb * RSU + jj) * 16, \
            (ga) + ((size_t)bb * NJ + jj) * NW); \
    } \
    _Pragma("unroll") \
    for (int s = 0; s < 8; s++) { \
        int u = tid + (s << 8), ii = u >> 4, jj = u & 15; \
        CPA(sB + (parsel) * B_BYTES + (uint32_t)(ii * RSU + jj) * 16, \
            (gb) + ((size_t)ii * NJ + jj) * 4); \
    } \
    asm volatile("cp.async.commit_group;" ::: "memory"); \
} while (0)

    // prologue
    STAGE(0, gA, gB);
    STAGE(1, gA + (size_t)KC * NW, gB + (size_t)KC * 4);
    gA += (size_t)2 * KC * NW;
    gB += (size_t)2 * KC * 4;

    const int lane = tid & 31, wid = tid >> 5;
    const int g = lane >> 2, q = lane & 3;
    const int wm = (wid >> 2) * 32;        // warp m-offset (0/32)
    const int wn = (wid & 3) * 32;         // warp n-offset (0..96)

    float acc[2][4][4][4];                 // [mt][nt][w][reg]
#pragma unroll
    for (int mt = 0; mt < 2; mt++)
#pragma unroll
        for (int nt = 0; nt < 4; nt++)
#pragma unroll
            for (int c = 0; c < 4; c++)
#pragma unroll
                for (int r = 0; r < 4; r++) acc[mt][nt][c][r] = 0.0f;

    for (int ch = 0; ch < NCH; ch++) {
        if (ch < NCH - 1) asm volatile("cp.async.wait_group 1;" ::: "memory");
        else              asm volatile("cp.async.wait_group 0;" ::: "memory");
        __syncthreads();

        const int par = ch & 1;
        const uint32_t pA = sbase + par * A_BYTES;
        const uint32_t pB = sB + par * B_BYTES;

#pragma unroll
        for (int ks = 0; ks < 2; ks++) {
            const int k0 = ks * 8;
            // B fragments: [nt][kpos], each float4 = 4 w's of (n=g, k=q{+4})
            float4 b4[4][2];
#pragma unroll
            for (int nt = 0; nt < 4; nt++) {
                const int ri = wn + nt * 8 + g;
                LDS128F(b4[nt][0], pB + (uint32_t)(ri * RSU + k0 + q) * 16);
                LDS128F(b4[nt][1], pB + (uint32_t)(ri * RSU + k0 + q + 4) * 16);
            }
#pragma unroll
            for (int mt = 0; mt < 2; mt++) {
                const int rb = wm + mt * 16;
                float4 a4[4];   // [pos]: (g,q), (g+8,q), (g,q+4), (g+8,q+4)
                LDS128F(a4[0], pA + (uint32_t)((rb + g) * RSU + k0 + q) * 16);
                LDS128F(a4[1], pA + (uint32_t)((rb + g + 8) * RSU + k0 + q) * 16);
                LDS128F(a4[2], pA + (uint32_t)((rb + g) * RSU + k0 + q + 4) * 16);
                LDS128F(a4[3], pA + (uint32_t)((rb + g + 8) * RSU + k0 + q + 4) * 16);
                const float* af0 = (const float*)&a4[0];
                const float* af1 = (const float*)&a4[1];
                const float* af2 = (const float*)&a4[2];
                const float* af3 = (const float*)&a4[3];
#pragma unroll
                for (int c = 0; c < 4; c++) {
                    const uint32_t ar0 = tf32u(af0[c]);
                    const uint32_t ar1 = tf32u(af1[c]);
                    const uint32_t ar2 = tf32u(af2[c]);
                    const uint32_t ar3 = tf32u(af3[c]);
#pragma unroll
                    for (int nt = 0; nt < 4; nt++) {
                        const float* bf0 = (const float*)&b4[nt][0];
                        const float* bf1 = (const float*)&b4[nt][1];
                        MMA_TF32(acc[mt][nt][c], ar0, ar1, ar2, ar3,
                                 __float_as_uint(bf0[c]), __float_as_uint(bf1[c]));
                    }
                }
            }
        }

        if (ch + 2 < NCH) {
            __syncthreads();   // all warps done reading buf[par]
            STAGE(par, gA, gB);
            gA += (size_t)KC * NW;
            gB += (size_t)KC * 4;
        }
    }

    // ---- epilogue: float4 over w, straight to out[b][i][w] ----
#pragma unroll
    for (int mt = 0; mt < 2; mt++) {
        const int row0 = b0 + wm + mt * 16 + g;
#pragma unroll
        for (int nt = 0; nt < 4; nt++) {
            const int col0 = i0 + wn + nt * 8 + 2 * q;
#pragma unroll
            for (int r = 0; r < 4; r++) {
                const int row = row0 + (r >> 1) * 8;
                const int col = col0 + (r & 1);
                float4 v = make_float4(acc[mt][nt][0][r], acc[mt][nt][1][r],
                                       acc[mt][nt][2][r], acc[mt][nt][3][r]);
                *(float4*)&out[((size_t)row * NI + col) * NW + wg * 4] = v;
            }
        }
    }
}

// ---------------------------------------------------------------------------
extern "C" void kernel_launch(void* const* d_in, const int* in_sizes, int n_in,
                              void* d_out, int out_size) {
    const float* input    = (const float*)d_in[0];  // [256,512,64]
    const float* phase    = (const float*)d_in[1];  // [512,512]
    const float* coupling = (const float*)d_in[2];  // [512,512]
    float* out            = (float*)d_out;          // [256,512,64]

    cudaFuncSetAttribute(gemm_kernel, cudaFuncAttributeMaxDynamicSharedMemorySize, SMEM_REQ);

    dropP_kernel<<<dim3(NJ / 256, NI), 256>>>(phase, coupling);
    gemm_kernel <<<dim3(NW / 4, NB / TM, NI / TN), 256, SMEM_REQ>>>(input, out);
}